// round 15
// baseline (speedup 1.0000x reference)
#include <cuda_runtime.h>
#include <cuda_bf16.h>
#include <math.h>
#include <cstdint>

// Problem constants
#define NB   2
#define NS   1024
#define NHID 1024
#define NH   16
#define NP   2
#define ND   64
#define NBH  32          // NB*NH
#define NSV  2048        // NS*NP
#define NM   2048        // NB*NS
#define ATT_SCALE 0.125f // 1/sqrt(64)

// Scratch (no cudaMalloc allowed)
__device__ float g_proj[3][NM * NHID];            // q/k/v projections
__device__ float g_attn[NBH * NSV * ND];          // SDPA output
__device__ float g_ctx [NM * NHID];               // collapsed context
// pre-split bf16 planes for flash: [hi/lo][bh, vpos, d]
__device__ __nv_bfloat16 g_q16[2][NBH * NSV * ND];
__device__ __nv_bfloat16 g_k16[2][NBH * NSV * ND];
__device__ __nv_bfloat16 g_v16[2][NBH * NSV * ND];

// bf16 warp MMA: D = A(16x16,row) @ B(16x8,col) + D, fp32 accum.
__device__ __forceinline__ void mma16816(float* c, const uint32_t* a, const uint32_t* b) {
    asm volatile(
        "mma.sync.aligned.m16n8k16.row.col.f32.bf16.bf16.f32 "
        "{%0,%1,%2,%3}, {%4,%5,%6,%7}, {%8,%9}, {%0,%1,%2,%3};"
        : "+f"(c[0]), "+f"(c[1]), "+f"(c[2]), "+f"(c[3])
        : "r"(a[0]), "r"(a[1]), "r"(a[2]), "r"(a[3]), "r"(b[0]), "r"(b[1]));
}

__device__ __forceinline__ uint32_t pack_hi2(float x, float y) {
    __nv_bfloat162 t(__float2bfloat16(x), __float2bfloat16(y));
    return *reinterpret_cast<uint32_t*>(&t);
}
__device__ __forceinline__ uint32_t pack_lo2(float x, float y) {
    __nv_bfloat16 hx = __float2bfloat16(x), hy = __float2bfloat16(y);
    __nv_bfloat162 t(__float2bfloat16(x - __bfloat162float(hx)),
                     __float2bfloat16(y - __bfloat162float(hy)));
    return *reinterpret_cast<uint32_t*>(&t);
}

// ---------------------------------------------------------------------------
// bf16x3 split-precision tensor-core GEMM (unchanged from R9 WIN).
// ---------------------------------------------------------------------------
#define BK      32
#define ASTR    40

__global__ __launch_bounds__(256, 2)
void gemm3_mma(const float* __restrict__ A,
               const float* __restrict__ B0, const float* __restrict__ B1,
               const float* __restrict__ B2,
               float* __restrict__ C0, float* __restrict__ C1, float* __restrict__ C2)
{
    const float* Bw = (blockIdx.z == 0) ? B0 : (blockIdx.z == 1) ? B1 : B2;
    float*       C  = (blockIdx.z == 0) ? C0 : (blockIdx.z == 1) ? C1 : C2;

    __shared__ __align__(16) __nv_bfloat16 sAh[128 * ASTR];
    __shared__ __align__(16) __nv_bfloat16 sAl[128 * ASTR];
    __shared__ __align__(16) __nv_bfloat16 sBh[128 * ASTR];
    __shared__ __align__(16) __nv_bfloat16 sBl[128 * ASTR];

    const int tid  = threadIdx.x;
    const int wid  = tid >> 5;
    const int lane = tid & 31;
    const int wm   = wid & 3;
    const int wn   = wid >> 2;
    const int row0 = blockIdx.y * 128;
    const int col0 = blockIdx.x * 128;

    const int fr = lane >> 2;
    const int cp = lane & 3;

    float acc[2][8][4];
#pragma unroll
    for (int mi = 0; mi < 2; mi++)
#pragma unroll
        for (int ni = 0; ni < 8; ni++)
#pragma unroll
            for (int j = 0; j < 4; j++) acc[mi][ni][j] = 0.f;

    for (int kb = 0; kb < NHID; kb += BK) {
        __syncthreads();
#pragma unroll
        for (int i = 0; i < 4; i++) {
            int idx = tid + i * 256;
            int row = idx >> 3;
            int jc  = (idx & 7) * 4;

            float4 va = *(const float4*)&A[(size_t)(row0 + row) * NHID + kb + jc];
            *(uint2*)&sAh[row * ASTR + jc] =
                make_uint2(pack_hi2(va.x, va.y), pack_hi2(va.z, va.w));
            *(uint2*)&sAl[row * ASTR + jc] =
                make_uint2(pack_lo2(va.x, va.y), pack_lo2(va.z, va.w));

            float4 vb = *(const float4*)&Bw[(size_t)(col0 + row) * NHID + kb + jc];
            *(uint2*)&sBh[row * ASTR + jc] =
                make_uint2(pack_hi2(vb.x, vb.y), pack_hi2(vb.z, vb.w));
            *(uint2*)&sBl[row * ASTR + jc] =
                make_uint2(pack_lo2(vb.x, vb.y), pack_lo2(vb.z, vb.w));
        }
        __syncthreads();

#pragma unroll
        for (int ks = 0; ks < 2; ks++) {
            const int k0 = ks * 16;
            uint32_t ah[2][4], al[2][4];
#pragma unroll
            for (int mi = 0; mi < 2; mi++) {
                int rb = wm * 32 + mi * 16;
                const __nv_bfloat16* p0 = &sAh[(rb + fr) * ASTR + k0 + cp * 2];
                const __nv_bfloat16* p1 = &sAh[(rb + fr + 8) * ASTR + k0 + cp * 2];
                ah[mi][0] = *(const uint32_t*)p0;
                ah[mi][1] = *(const uint32_t*)p1;
                ah[mi][2] = *(const uint32_t*)(p0 + 8);
                ah[mi][3] = *(const uint32_t*)(p1 + 8);
                const __nv_bfloat16* q0 = &sAl[(rb + fr) * ASTR + k0 + cp * 2];
                const __nv_bfloat16* q1 = &sAl[(rb + fr + 8) * ASTR + k0 + cp * 2];
                al[mi][0] = *(const uint32_t*)q0;
                al[mi][1] = *(const uint32_t*)q1;
                al[mi][2] = *(const uint32_t*)(q0 + 8);
                al[mi][3] = *(const uint32_t*)(q1 + 8);
            }
#pragma unroll
            for (int ni = 0; ni < 8; ni++) {
                int nb = wn * 64 + ni * 8;
                const __nv_bfloat16* pb = &sBh[(nb + fr) * ASTR + k0 + cp * 2];
                const __nv_bfloat16* ql = &sBl[(nb + fr) * ASTR + k0 + cp * 2];
                uint32_t bh[2] = { *(const uint32_t*)pb, *(const uint32_t*)(pb + 8) };
                uint32_t bl[2] = { *(const uint32_t*)ql, *(const uint32_t*)(ql + 8) };
#pragma unroll
                for (int mi = 0; mi < 2; mi++) {
                    mma16816(acc[mi][ni], ah[mi], bh);
                    mma16816(acc[mi][ni], ah[mi], bl);
                    mma16816(acc[mi][ni], al[mi], bh);
                }
            }
        }
    }

#pragma unroll
    for (int mi = 0; mi < 2; mi++) {
#pragma unroll
        for (int ni = 0; ni < 8; ni++) {
            int row = row0 + wm * 32 + mi * 16 + fr;
            int col = col0 + wn * 64 + ni * 8 + cp * 2;
            *(float2*)&C[(size_t)row * NHID + col] =
                make_float2(acc[mi][ni][0], acc[mi][ni][1]);
            *(float2*)&C[(size_t)(row + 8) * NHID + col] =
                make_float2(acc[mi][ni][2], acc[mi][ni][3]);
        }
    }
}

// ---------------------------------------------------------------------------
// Head mixing + bf16 hi/lo pre-split (flash consumes the bf16 planes).
// ---------------------------------------------------------------------------
__global__ __launch_bounds__(256)
void mix_kernel(const float* __restrict__ aq, const float* __restrict__ ak,
                const float* __restrict__ av)
{
    __shared__ float srow[3][1024];
    __shared__ float sal[3][512];

    const int tid = threadIdx.x;
    const int bn  = blockIdx.x;
    const int b   = bn >> 10;
    const int n   = bn & 1023;

#pragma unroll
    for (int t = 0; t < 3; t++)
#pragma unroll
        for (int r = 0; r < 4; r++)
            srow[t][tid + r * 256] = g_proj[t][(size_t)bn * NHID + tid + r * 256];

    const float* al[3] = { aq, ak, av };
#pragma unroll
    for (int t = 0; t < 3; t++) {
        sal[t][tid]       = al[t][tid];
        sal[t][tid + 256] = al[t][tid + 256];
    }
    __syncthreads();

    const int d   = tid & 63;
    const int hp0 = tid >> 6;

#pragma unroll
    for (int t = 0; t < 3; t++) {
#pragma unroll
        for (int r = 0; r < 8; r++) {
            int hp = hp0 + r * 4;
            int h = hp >> 1, p = hp & 1;
            float s = 0.f;
#pragma unroll
            for (int m = 0; m < 16; m++)
                s += sal[t][(m * 16 + h) * 2 + p] * srow[t][m * 64 + d];
            size_t gi = ((size_t)(b * 16 + h) * NSV + (n * 2 + p)) * ND + d;
            __nv_bfloat16 hi = __float2bfloat16(s);
            __nv_bfloat16 lo = __float2bfloat16(s - __bfloat162float(hi));
            if (t == 0)      { g_q16[0][gi] = hi; g_q16[1][gi] = lo; }
            else if (t == 1) { g_k16[0][gi] = hi; g_k16[1][gi] = lo; }
            else             { g_v16[0][gi] = hi; g_v16[1][gi] = lo; }
        }
    }
}

// ---------------------------------------------------------------------------
// Flash attention, bf16x3 tensor cores. v3: occupancy 2 (prefetch removed,
// co-resident CTA hides LDG latency; ~96 regs/thread fits 2 CTAs/SM).
// BQ=128 (8 warps x m16), BK=64; smem stride 72; V transposed w/ XOR swizzle.
// ---------------------------------------------------------------------------
#define FSTR 72

__global__ __launch_bounds__(256, 2)
void flash_mma(const __nv_bfloat16* __restrict__ Gqh, const __nv_bfloat16* __restrict__ Gql,
               const __nv_bfloat16* __restrict__ Gkh, const __nv_bfloat16* __restrict__ Gkl,
               const __nv_bfloat16* __restrict__ Gvh, const __nv_bfloat16* __restrict__ Gvl,
               float* __restrict__ O)
{
    extern __shared__ __nv_bfloat16 fsm[];
    __nv_bfloat16* Qh = fsm;                    // [128][72]
    __nv_bfloat16* Ql = Qh + 128 * FSTR;
    __nv_bfloat16* Kh = Ql + 128 * FSTR;        // [64][72] (row=kpos, col=d)
    __nv_bfloat16* Kl = Kh + 64 * FSTR;
    __nv_bfloat16* Vh = Kl + 64 * FSTR;         // [64][72] (row=d, col=kpos^swz)
    __nv_bfloat16* Vl = Vh + 64 * FSTR;

    const int tid  = threadIdx.x;
    const int wid  = tid >> 5;
    const int lane = tid & 31;
    const int fr   = lane >> 2;
    const int cp   = lane & 3;
    const int qt   = 15 - blockIdx.x;           // heavy tiles first
    const int bh   = blockIdx.y;

    // Q tile copy (bf16 planes, no conversion)
    {
        const __nv_bfloat16* qh = Gqh + ((size_t)bh * NSV + qt * 128) * ND;
        const __nv_bfloat16* ql = Gql + ((size_t)bh * NSV + qt * 128) * ND;
#pragma unroll
        for (int i = 0; i < 4; i++) {
            int idx = tid + i * 256;            // 0..1023 uint4 slots
            int row = idx >> 3;
            int jc  = (idx & 7) * 8;
            *(uint4*)&Qh[row * FSTR + jc] = *(const uint4*)&qh[row * ND + jc];
            *(uint4*)&Ql[row * FSTR + jc] = *(const uint4*)&ql[row * ND + jc];
        }
    }

    float m0 = -1e30f, m1 = -1e30f, l0 = 0.f, l1 = 0.f;
    float o[8][4];
#pragma unroll
    for (int nf = 0; nf < 8; nf++)
#pragma unroll
        for (int j = 0; j < 4; j++) o[nf][j] = 0.f;

    const int rowg0 = qt * 128 + wid * 16 + fr;
    const int rowg1 = rowg0 + 8;
    const int kts = 2 * qt + 2;

    for (int kt = 0; kt < kts; kt++) {
        const __nv_bfloat16* kh = Gkh + ((size_t)bh * NSV + kt * 64) * ND;
        const __nv_bfloat16* kl = Gkl + ((size_t)bh * NSV + kt * 64) * ND;
        const __nv_bfloat16* vh = Gvh + ((size_t)bh * NSV + kt * 64) * ND;
        const __nv_bfloat16* vl = Gvl + ((size_t)bh * NSV + kt * 64) * ND;

        __syncthreads();   // prior iter's fragment reads done (covers Q fill)
#pragma unroll
        for (int i = 0; i < 2; i++) {
            int idx = tid + i * 256;            // 0..511 uint4 slots
            int row = idx >> 3;                 // kpos
            int jc  = (idx & 7) * 8;            // d base
            int off = row * ND + jc;
            *(uint4*)&Kh[row * FSTR + jc] = *(const uint4*)&kh[off];
            *(uint4*)&Kl[row * FSTR + jc] = *(const uint4*)&kl[off];
            uint4 v4h = *(const uint4*)&vh[off];
            uint4 v4l = *(const uint4*)&vl[off];
            const __nv_bfloat16* ph = (const __nv_bfloat16*)&v4h;
            const __nv_bfloat16* pl = (const __nv_bfloat16*)&v4l;
#pragma unroll
            for (int e = 0; e < 8; e++) {
                int d  = jc + e;
                int kx = row ^ (((d >> 2) & 7) << 3);
                Vh[d * FSTR + kx] = ph[e];
                Vl[d * FSTR + kx] = pl[e];
            }
        }
        __syncthreads();

        // ---- S = Q @ K^T ----
        float s[8][4];
#pragma unroll
        for (int nf = 0; nf < 8; nf++)
#pragma unroll
            for (int j = 0; j < 4; j++) s[nf][j] = 0.f;

#pragma unroll
        for (int ds = 0; ds < 4; ds++) {
            const int k0 = ds * 16;
            const int rb = wid * 16;
            const __nv_bfloat16* p0 = &Qh[(rb + fr) * FSTR + k0 + cp * 2];
            const __nv_bfloat16* p1 = &Qh[(rb + fr + 8) * FSTR + k0 + cp * 2];
            uint32_t ah[4] = { *(const uint32_t*)p0, *(const uint32_t*)p1,
                               *(const uint32_t*)(p0 + 8), *(const uint32_t*)(p1 + 8) };
            const __nv_bfloat16* q0 = &Ql[(rb + fr) * FSTR + k0 + cp * 2];
            const __nv_bfloat16* q1 = &Ql[(rb + fr + 8) * FSTR + k0 + cp * 2];
            uint32_t al[4] = { *(const uint32_t*)q0, *(const uint32_t*)q1,
                               *(const uint32_t*)(q0 + 8), *(const uint32_t*)(q1 + 8) };
#pragma unroll
            for (int nf = 0; nf < 8; nf++) {
                int nb = nf * 8;
                const __nv_bfloat16* pb = &Kh[(nb + fr) * FSTR + k0 + cp * 2];
                const __nv_bfloat16* ql = &Kl[(nb + fr) * FSTR + k0 + cp * 2];
                uint32_t bh[2] = { *(const uint32_t*)pb, *(const uint32_t*)(pb + 8) };
                uint32_t bl[2] = { *(const uint32_t*)ql, *(const uint32_t*)(ql + 8) };
                mma16816(s[nf], ah, bh);
                mma16816(s[nf], ah, bl);
                mma16816(s[nf], al, bh);
            }
        }

        // ---- scale + causal mask ----
#pragma unroll
        for (int nf = 0; nf < 8; nf++) {
            int c0 = kt * 64 + nf * 8 + cp * 2;
            s[nf][0] = (c0     <= rowg0) ? s[nf][0] * ATT_SCALE : -1e30f;
            s[nf][1] = (c0 + 1 <= rowg0) ? s[nf][1] * ATT_SCALE : -1e30f;
            s[nf][2] = (c0     <= rowg1) ? s[nf][2] * ATT_SCALE : -1e30f;
            s[nf][3] = (c0 + 1 <= rowg1) ? s[nf][3] * ATT_SCALE : -1e30f;
        }

        // ---- online softmax ----
        float mx0 = -1e30f, mx1 = -1e30f;
#pragma unroll
        for (int nf = 0; nf < 8; nf++) {
            mx0 = fmaxf(mx0, fmaxf(s[nf][0], s[nf][1]));
            mx1 = fmaxf(mx1, fmaxf(s[nf][2], s[nf][3]));
        }
#pragma unroll
        for (int off = 1; off < 4; off <<= 1) {
            mx0 = fmaxf(mx0, __shfl_xor_sync(0xffffffffu, mx0, off));
            mx1 = fmaxf(mx1, __shfl_xor_sync(0xffffffffu, mx1, off));
        }
        float mn0 = fmaxf(m0, mx0), mn1 = fmaxf(m1, mx1);
        float cr0 = __expf(m0 - mn0), cr1 = __expf(m1 - mn1);
        float sm0 = 0.f, sm1 = 0.f;
#pragma unroll
        for (int nf = 0; nf < 8; nf++) {
            s[nf][0] = __expf(s[nf][0] - mn0);
            s[nf][1] = __expf(s[nf][1] - mn0);
            s[nf][2] = __expf(s[nf][2] - mn1);
            s[nf][3] = __expf(s[nf][3] - mn1);
            sm0 += s[nf][0] + s[nf][1];
            sm1 += s[nf][2] + s[nf][3];
        }
#pragma unroll
        for (int off = 1; off < 4; off <<= 1) {
            sm0 += __shfl_xor_sync(0xffffffffu, sm0, off);
            sm1 += __shfl_xor_sync(0xffffffffu, sm1, off);
        }
        l0 = l0 * cr0 + sm0;  m0 = mn0;
        l1 = l1 * cr1 + sm1;  m1 = mn1;
#pragma unroll
        for (int nf = 0; nf < 8; nf++) {
            o[nf][0] *= cr0; o[nf][1] *= cr0;
            o[nf][2] *= cr1; o[nf][3] *= cr1;
        }

        // ---- O += P @ V ----
#pragma unroll
        for (int ks = 0; ks < 4; ks++) {
            const int k0 = ks * 16;
            uint32_t ph[4], pl[4];
            ph[0] = pack_hi2(s[2*ks][0],   s[2*ks][1]);
            ph[1] = pack_hi2(s[2*ks][2],   s[2*ks][3]);
            ph[2] = pack_hi2(s[2*ks+1][0], s[2*ks+1][1]);
            ph[3] = pack_hi2(s[2*ks+1][2], s[2*ks+1][3]);
            pl[0] = pack_lo2(s[2*ks][0],   s[2*ks][1]);
            pl[1] = pack_lo2(s[2*ks][2],   s[2*ks][3]);
            pl[2] = pack_lo2(s[2*ks+1][0], s[2*ks+1][1]);
            pl[3] = pack_lo2(s[2*ks+1][2], s[2*ks+1][3]);
#pragma unroll
            for (int nf = 0; nf < 8; nf++) {
                int d  = nf * 8 + fr;
                int sw = ((d >> 2) & 7) << 3;
                int kx0 = (k0 + cp * 2) ^ sw;
                int kx1 = (k0 + cp * 2 + 8) ^ sw;
                uint32_t bh[2] = { *(const uint32_t*)&Vh[d * FSTR + kx0],
                                   *(const uint32_t*)&Vh[d * FSTR + kx1] };
                uint32_t bl[2] = { *(const uint32_t*)&Vl[d * FSTR + kx0],
                                   *(const uint32_t*)&Vl[d * FSTR + kx1] };
                mma16816(o[nf], ph, bh);
                mma16816(o[nf], ph, bl);
                mma16816(o[nf], pl, bh);
            }
        }
    }

    // ---- normalize + store ----
    float i0 = 1.0f / l0, i1 = 1.0f / l1;
    float* Op = O + ((size_t)bh * NSV) * ND;
#pragma unroll
    for (int nf = 0; nf < 8; nf++) {
        int col = nf * 8 + cp * 2;
        *(float2*)&Op[(size_t)rowg0 * ND + col] = make_float2(o[nf][0] * i0, o[nf][1] * i0);
        *(float2*)&Op[(size_t)rowg1 * ND + col] = make_float2(o[nf][2] * i1, o[nf][3] * i1);
    }
}

// ---------------------------------------------------------------------------
// Collapse pseudo-heads (unchanged)
// ---------------------------------------------------------------------------
__global__ __launch_bounds__(256)
void collapse_kernel(const float* __restrict__ cw)
{
    __shared__ float sa[2048];
    __shared__ float sc[512];

    const int tid = threadIdx.x;
    const int bn  = blockIdx.x;
    const int b   = bn >> 10;
    const int n   = bn & 1023;

#pragma unroll
    for (int r = 0; r < 8; r++) {
        int idx = tid + r * 256;
        int mp = idx >> 6, d = idx & 63;
        int m = mp >> 1, p = mp & 1;
        sa[idx] = g_attn[((size_t)(b * 16 + m) * NSV + (n * 2 + p)) * ND + d];
    }
    sc[tid]       = cw[tid];
    sc[tid + 256] = cw[tid + 256];
    __syncthreads();

    const int d  = tid & 63;
    const int h0 = tid >> 6;
#pragma unroll
    for (int r = 0; r < 4; r++) {
        int h = h0 + r * 4;
        float s = 0.f;
#pragma unroll
        for (int o = 0; o < 32; o++)
            s += sc[h * 32 + o] * sa[o * 64 + d];
        g_ctx[(size_t)bn * NHID + h * 64 + d] = s;
    }
}

// ---------------------------------------------------------------------------
extern "C" void kernel_launch(void* const* d_in, const int* in_sizes, int n_in,
                              void* d_out, int out_size)
{
    const float* x  = (const float*)d_in[0];
    const float* Wq = (const float*)d_in[1];
    const float* Wk = (const float*)d_in[2];
    const float* Wv = (const float*)d_in[3];
    const float* Wo = (const float*)d_in[4];
    const float* aq = (const float*)d_in[5];
    const float* ak = (const float*)d_in[6];
    const float* av = (const float*)d_in[7];
    const float* cw = (const float*)d_in[8];
    float* out = (float*)d_out;

    float *pProj, *pAttn, *pCtx;
    __nv_bfloat16 *pQ16, *pK16, *pV16;
    cudaGetSymbolAddress((void**)&pProj, g_proj);
    cudaGetSymbolAddress((void**)&pAttn, g_attn);
    cudaGetSymbolAddress((void**)&pCtx,  g_ctx);
    cudaGetSymbolAddress((void**)&pQ16,  g_q16);
    cudaGetSymbolAddress((void**)&pK16,  g_k16);
    cudaGetSymbolAddress((void**)&pV16,  g_v16);
    const size_t PLANE = (size_t)NBH * NSV * ND;

    // 1) QKV projection (tensor cores, bf16x3)
    dim3 gProj(NHID / 128, NM / 128, 3);
    gemm3_mma<<<gProj, 256>>>(x, Wq, Wk, Wv,
                              pProj,
                              pProj + (size_t)NM * NHID,
                              pProj + 2 * (size_t)NM * NHID);

    // 2) head mixing + bf16 hi/lo pre-split
    mix_kernel<<<NM, 256>>>(aq, ak, av);

    // 3) causal flash attention (tensor cores, bf16x3, occupancy 2)
    const int fSmem = (2 * 128 + 4 * 64) * FSTR * (int)sizeof(__nv_bfloat16); // 73728
    cudaFuncSetAttribute(flash_mma,
                         cudaFuncAttributeMaxDynamicSharedMemorySize, fSmem);
    dim3 gF(NSV / 128, NBH, 1);
    flash_mma<<<gF, 256, fSmem>>>(pQ16, pQ16 + PLANE,
                                  pK16, pK16 + PLANE,
                                  pV16, pV16 + PLANE,
                                  pAttn);

    // 4) collapse pseudo-heads
    collapse_kernel<<<NM, 256>>>(cw);

    // 5) output projection (tensor cores)
    dim3 gOut(NHID / 128, NM / 128, 1);
    gemm3_mma<<<gOut, 256>>>(pCtx, Wo, Wo, Wo, out, out, out);
}